// round 1
// baseline (speedup 1.0000x reference)
#include <cuda_runtime.h>
#include <math.h>

#define B_ 8
#define S_ 2048
#define D_ 1024
#define NROWS (B_ * S_)

// Scratch (device globals: allowed; no runtime allocation)
__device__ float g_q[(size_t)NROWS * D_];            // 64 MB
__device__ float g_k[(size_t)NROWS * D_];            // 64 MB
__device__ float g_v[(size_t)NROWS * D_];            // 64 MB
__device__ float g_p[(size_t)B_ * S_ * S_];          // 128 MB (attn probs)

// ---------------------------------------------------------------------------
// Kernel 1: fused QKV projection.  C = A @ W + b for each of q/k/v (grid.z)
// 128x128 block tile, BK=8, 256 threads, 8x8 per-thread, double-buffered SMEM.
// ---------------------------------------------------------------------------
__global__ __launch_bounds__(256) void qkv_gemm_kernel(
    const float* __restrict__ q_in, const float* __restrict__ k_in,
    const float* __restrict__ v_in,
    const float* __restrict__ Wq, const float* __restrict__ bq,
    const float* __restrict__ Wk, const float* __restrict__ bk,
    const float* __restrict__ Wv, const float* __restrict__ bv)
{
    const int which = blockIdx.z;
    const float* A    = (which == 0) ? q_in : (which == 1) ? k_in : v_in;
    const float* W    = (which == 0) ? Wq   : (which == 1) ? Wk   : Wv;
    const float* bias = (which == 0) ? bq   : (which == 1) ? bk   : bv;
    float* C          = (which == 0) ? g_q  : (which == 1) ? g_k  : g_v;

    __shared__ float As[2][8][128];
    __shared__ float Bs[2][8][128];

    const int tid  = threadIdx.x;
    const int trow = (tid >> 4) << 3;     // 0..120
    const int tcol = (tid & 15) << 3;

    const int m0 = blockIdx.y << 7;
    const int n0 = blockIdx.x << 7;

    const int a_row = tid >> 1;
    const int a_col = (tid & 1) << 2;
    const int b_row = tid >> 5;           // 0..7
    const int b_col = (tid & 31) << 2;    // 0..124

    const float* Ag = A + (size_t)(m0 + a_row) * D_ + a_col;
    const float* Bg = W + (size_t)b_row * D_ + n0 + b_col;

    float acc[8][8];
#pragma unroll
    for (int i = 0; i < 8; i++)
#pragma unroll
        for (int j = 0; j < 8; j++) acc[i][j] = 0.f;

    // preload tile 0
    {
        float4 av = *(const float4*)Ag;
        float4 bv = *(const float4*)Bg;
        As[0][a_col + 0][a_row] = av.x;
        As[0][a_col + 1][a_row] = av.y;
        As[0][a_col + 2][a_row] = av.z;
        As[0][a_col + 3][a_row] = av.w;
        *(float4*)&Bs[0][b_row][b_col] = bv;
    }
    __syncthreads();

    const int KT = D_ / 8;
    for (int kt = 0; kt < KT; ++kt) {
        const int buf = kt & 1;
        float4 av2, bv2;
        const bool more = (kt + 1 < KT);
        if (more) {
            av2 = *(const float4*)(Ag + (kt + 1) * 8);
            bv2 = *(const float4*)(Bg + (size_t)(kt + 1) * 8 * D_);
        }
#pragma unroll
        for (int kk = 0; kk < 8; ++kk) {
            float af[8], bf[8];
            *(float4*)(af)     = *(const float4*)&As[buf][kk][trow];
            *(float4*)(af + 4) = *(const float4*)&As[buf][kk][trow + 4];
            *(float4*)(bf)     = *(const float4*)&Bs[buf][kk][tcol];
            *(float4*)(bf + 4) = *(const float4*)&Bs[buf][kk][tcol + 4];
#pragma unroll
            for (int i = 0; i < 8; i++)
#pragma unroll
                for (int j = 0; j < 8; j++) acc[i][j] += af[i] * bf[j];
        }
        if (more) {
            const int nb = buf ^ 1;
            As[nb][a_col + 0][a_row] = av2.x;
            As[nb][a_col + 1][a_row] = av2.y;
            As[nb][a_col + 2][a_row] = av2.z;
            As[nb][a_col + 3][a_row] = av2.w;
            *(float4*)&Bs[nb][b_row][b_col] = bv2;
        }
        __syncthreads();
    }

    float bset[8];
    *(float4*)(bset)     = *(const float4*)&bias[n0 + tcol];
    *(float4*)(bset + 4) = *(const float4*)&bias[n0 + tcol + 4];

#pragma unroll
    for (int i = 0; i < 8; i++) {
        float* Crow = C + (size_t)(m0 + trow + i) * D_ + n0 + tcol;
        float4 o0 = make_float4(acc[i][0] + bset[0], acc[i][1] + bset[1],
                                acc[i][2] + bset[2], acc[i][3] + bset[3]);
        float4 o1 = make_float4(acc[i][4] + bset[4], acc[i][5] + bset[5],
                                acc[i][6] + bset[6], acc[i][7] + bset[7]);
        *(float4*)(Crow)     = o0;
        *(float4*)(Crow + 4) = o1;
    }
}

// ---------------------------------------------------------------------------
// Kernel 2: scores = Q @ K^T * (1/32) per batch; only lower-tri blocks.
// NT GEMM: both operands row-major [S, D].
// ---------------------------------------------------------------------------
__global__ __launch_bounds__(256) void scores_kernel()
{
    const int bn = blockIdx.x;   // key block
    const int bm = blockIdx.y;   // query block
    const int b  = blockIdx.z;
    if (bn > bm) return;         // strictly upper-triangular block: skip

    __shared__ float As[2][8][128];
    __shared__ float Bs[2][8][128];

    const int tid  = threadIdx.x;
    const int trow = (tid >> 4) << 3;
    const int tcol = (tid & 15) << 3;

    const int m0 = bm << 7;
    const int n0 = bn << 7;

    const int a_row = tid >> 1;
    const int a_col = (tid & 1) << 2;

    const float* Qb = g_q + (size_t)b * S_ * D_;
    const float* Kb = g_k + (size_t)b * S_ * D_;

    const float* Ag = Qb + (size_t)(m0 + a_row) * D_ + a_col;
    const float* Bg = Kb + (size_t)(n0 + a_row) * D_ + a_col;   // NT: same pattern

    float acc[8][8];
#pragma unroll
    for (int i = 0; i < 8; i++)
#pragma unroll
        for (int j = 0; j < 8; j++) acc[i][j] = 0.f;

    {
        float4 av = *(const float4*)Ag;
        float4 bv = *(const float4*)Bg;
        As[0][a_col + 0][a_row] = av.x;
        As[0][a_col + 1][a_row] = av.y;
        As[0][a_col + 2][a_row] = av.z;
        As[0][a_col + 3][a_row] = av.w;
        Bs[0][a_col + 0][a_row] = bv.x;
        Bs[0][a_col + 1][a_row] = bv.y;
        Bs[0][a_col + 2][a_row] = bv.z;
        Bs[0][a_col + 3][a_row] = bv.w;
    }
    __syncthreads();

    const int KT = D_ / 8;
    for (int kt = 0; kt < KT; ++kt) {
        const int buf = kt & 1;
        float4 av2, bv2;
        const bool more = (kt + 1 < KT);
        if (more) {
            av2 = *(const float4*)(Ag + (kt + 1) * 8);
            bv2 = *(const float4*)(Bg + (kt + 1) * 8);
        }
#pragma unroll
        for (int kk = 0; kk < 8; ++kk) {
            float af[8], bf[8];
            *(float4*)(af)     = *(const float4*)&As[buf][kk][trow];
            *(float4*)(af + 4) = *(const float4*)&As[buf][kk][trow + 4];
            *(float4*)(bf)     = *(const float4*)&Bs[buf][kk][tcol];
            *(float4*)(bf + 4) = *(const float4*)&Bs[buf][kk][tcol + 4];
#pragma unroll
            for (int i = 0; i < 8; i++)
#pragma unroll
                for (int j = 0; j < 8; j++) acc[i][j] += af[i] * bf[j];
        }
        if (more) {
            const int nb = buf ^ 1;
            As[nb][a_col + 0][a_row] = av2.x;
            As[nb][a_col + 1][a_row] = av2.y;
            As[nb][a_col + 2][a_row] = av2.z;
            As[nb][a_col + 3][a_row] = av2.w;
            Bs[nb][a_col + 0][a_row] = bv2.x;
            Bs[nb][a_col + 1][a_row] = bv2.y;
            Bs[nb][a_col + 2][a_row] = bv2.z;
            Bs[nb][a_col + 3][a_row] = bv2.w;
        }
        __syncthreads();
    }

    float* Pb = g_p + (size_t)b * S_ * S_;
    const float scale = 0.03125f;   // 1/sqrt(1024)
#pragma unroll
    for (int i = 0; i < 8; i++) {
        float* Prow = Pb + (size_t)(m0 + trow + i) * S_ + n0 + tcol;
        float4 o0 = make_float4(acc[i][0] * scale, acc[i][1] * scale,
                                acc[i][2] * scale, acc[i][3] * scale);
        float4 o1 = make_float4(acc[i][4] * scale, acc[i][5] * scale,
                                acc[i][6] * scale, acc[i][7] * scale);
        *(float4*)(Prow)     = o0;
        *(float4*)(Prow + 4) = o1;
    }
}

// ---------------------------------------------------------------------------
// Kernel 3: causal softmax over each row; zero-fill up to the 128 boundary
// so the AV GEMM's truncated K-loop reads clean data in the diagonal block.
// ---------------------------------------------------------------------------
__global__ __launch_bounds__(256) void softmax_kernel()
{
    const int m = blockIdx.x;
    const int b = blockIdx.y;
    float* row = g_p + ((size_t)b * S_ + m) * S_;
    const int L = m + 1;
    const int Lpad = ((m >> 7) + 1) << 7;

    __shared__ float sm[S_];
    __shared__ float red[256];
    const int tid = threadIdx.x;

    float mx = -INFINITY;
    for (int i = tid; i < L; i += 256) {
        float v = row[i];
        sm[i] = v;
        mx = fmaxf(mx, v);
    }
    red[tid] = mx;
    __syncthreads();
    for (int s = 128; s > 0; s >>= 1) {
        if (tid < s) red[tid] = fmaxf(red[tid], red[tid + s]);
        __syncthreads();
    }
    mx = red[0];
    __syncthreads();

    float sum = 0.f;
    for (int i = tid; i < L; i += 256) {
        float e = __expf(sm[i] - mx);
        sm[i] = e;
        sum += e;
    }
    red[tid] = sum;
    __syncthreads();
    for (int s = 128; s > 0; s >>= 1) {
        if (tid < s) red[tid] += red[tid + s];
        __syncthreads();
    }
    const float inv = 1.f / red[0];
    __syncthreads();

    for (int i = tid; i < Lpad; i += 256)
        row[i] = (i < L) ? sm[i] * inv : 0.f;
}

// ---------------------------------------------------------------------------
// Kernel 4: out = P @ V per batch (NN GEMM), K-loop truncated at diagonal.
// ---------------------------------------------------------------------------
__global__ __launch_bounds__(256) void av_kernel(float* __restrict__ out)
{
    const int bn = blockIdx.x;   // D block (8)
    const int bm = blockIdx.y;   // query block (16)
    const int b  = blockIdx.z;

    __shared__ float As[2][8][128];
    __shared__ float Bs[2][8][128];

    const int tid  = threadIdx.x;
    const int trow = (tid >> 4) << 3;
    const int tcol = (tid & 15) << 3;

    const int m0 = bm << 7;
    const int n0 = bn << 7;

    const int a_row = tid >> 1;
    const int a_col = (tid & 1) << 2;
    const int b_row = tid >> 5;
    const int b_col = (tid & 31) << 2;

    const float* P = g_p + (size_t)b * S_ * S_;
    const float* V = g_v + (size_t)b * S_ * D_;

    const float* Ag = P + (size_t)(m0 + a_row) * S_ + a_col;
    const float* Bg = V + (size_t)b_row * D_ + n0 + b_col;

    float acc[8][8];
#pragma unroll
    for (int i = 0; i < 8; i++)
#pragma unroll
        for (int j = 0; j < 8; j++) acc[i][j] = 0.f;

    {
        float4 av = *(const float4*)Ag;
        float4 bv = *(const float4*)Bg;
        As[0][a_col + 0][a_row] = av.x;
        As[0][a_col + 1][a_row] = av.y;
        As[0][a_col + 2][a_row] = av.z;
        As[0][a_col + 3][a_row] = av.w;
        *(float4*)&Bs[0][b_row][b_col] = bv;
    }
    __syncthreads();

    const int KT = (bm + 1) * 16;   // causal: k <= (bm+1)*128
    for (int kt = 0; kt < KT; ++kt) {
        const int buf = kt & 1;
        float4 av2, bv2;
        const bool more = (kt + 1 < KT);
        if (more) {
            av2 = *(const float4*)(Ag + (kt + 1) * 8);
            bv2 = *(const float4*)(Bg + (size_t)(kt + 1) * 8 * D_);
        }
#pragma unroll
        for (int kk = 0; kk < 8; ++kk) {
            float af[8], bf[8];
            *(float4*)(af)     = *(const float4*)&As[buf][kk][trow];
            *(float4*)(af + 4) = *(const float4*)&As[buf][kk][trow + 4];
            *(float4*)(bf)     = *(const float4*)&Bs[buf][kk][tcol];
            *(float4*)(bf + 4) = *(const float4*)&Bs[buf][kk][tcol + 4];
#pragma unroll
            for (int i = 0; i < 8; i++)
#pragma unroll
                for (int j = 0; j < 8; j++) acc[i][j] += af[i] * bf[j];
        }
        if (more) {
            const int nb = buf ^ 1;
            As[nb][a_col + 0][a_row] = av2.x;
            As[nb][a_col + 1][a_row] = av2.y;
            As[nb][a_col + 2][a_row] = av2.z;
            As[nb][a_col + 3][a_row] = av2.w;
            *(float4*)&Bs[nb][b_row][b_col] = bv2;
        }
        __syncthreads();
    }

    float* Ob = out + (size_t)b * S_ * D_;
#pragma unroll
    for (int i = 0; i < 8; i++) {
        float* Orow = Ob + (size_t)(m0 + trow + i) * D_ + n0 + tcol;
        *(float4*)(Orow)     = make_float4(acc[i][0], acc[i][1], acc[i][2], acc[i][3]);
        *(float4*)(Orow + 4) = make_float4(acc[i][4], acc[i][5], acc[i][6], acc[i][7]);
    }
}

// ---------------------------------------------------------------------------
extern "C" void kernel_launch(void* const* d_in, const int* in_sizes, int n_in,
                              void* d_out, int out_size)
{
    const float* query = (const float*)d_in[0];
    const float* key   = (const float*)d_in[1];
    const float* value = (const float*)d_in[2];
    // d_in[3] = mask (causal, known statically; unused)
    const float* Wq = (const float*)d_in[4];
    const float* bq = (const float*)d_in[5];
    const float* Wk = (const float*)d_in[6];
    const float* bk = (const float*)d_in[7];
    const float* Wv = (const float*)d_in[8];
    const float* bv = (const float*)d_in[9];
    float* out = (float*)d_out;

    dim3 block(256);

    // Phase A: Q/K/V projections (fused into one launch via grid.z)
    qkv_gemm_kernel<<<dim3(D_ / 128, NROWS / 128, 3), block>>>(
        query, key, value, Wq, bq, Wk, bk, Wv, bv);

    // Phase B: causal scores
    scores_kernel<<<dim3(S_ / 128, S_ / 128, B_), block>>>();

    // Phase C: row softmax
    softmax_kernel<<<dim3(S_, B_), block>>>();

    // Phase D: out = P @ V
    av_kernel<<<dim3(D_ / 128, S_ / 128, B_), block>>>(out);
}

// round 3
// speedup vs baseline: 2.9018x; 2.9018x over previous
#include <cuda_runtime.h>
#include <math.h>
#include <stdint.h>

#define B_ 8
#define S_ 2048
#define D_ 1024
#define NROWS (B_ * S_)

// Scratch (device globals: allowed; no runtime allocation)
__device__ float g_q[(size_t)NROWS * D_];
__device__ float g_k[(size_t)NROWS * D_];
__device__ float g_v[(size_t)NROWS * D_];
__device__ float g_p[(size_t)B_ * S_ * S_];

// ---------------------------------------------------------------------------
// tf32 helpers (base-ISA PTX only; no tcgen05 — harness targets sm_103 non-'a')
// ---------------------------------------------------------------------------
__device__ __forceinline__ float to_tf32(float x) {
    uint32_t r;
    asm("cvt.rna.tf32.f32 %0, %1;" : "=r"(r) : "f"(x));
    return __uint_as_float(r);
}

#define MMA_TF32(c, a, b)                                                     \
    asm volatile(                                                             \
        "mma.sync.aligned.m16n8k8.row.col.f32.tf32.tf32.f32 "                 \
        "{%0,%1,%2,%3}, {%4,%5,%6,%7}, {%8,%9}, {%0,%1,%2,%3};"               \
        : "+f"((c)[0]), "+f"((c)[1]), "+f"((c)[2]), "+f"((c)[3])              \
        : "r"((a)[0]), "r"((a)[1]), "r"((a)[2]), "r"((a)[3]),                 \
          "r"((b)[0]), "r"((b)[1]))

// SMEM strides (floats). A/BT tiles: [rows][16k] stride 20 (20g+t conflict-free,
// 80B row = 5*16 so float4 STS aligned). BN tiles: [16k][128n] stride 136
// (8t+g conflict-free, 544B row = 34*16 aligned).
#define STA 20
#define STBN 136

#define OFF_A0 0
#define OFF_A1 2560
#define OFF_B0 5120
#define OFF_B1 7680
#define SM_FLOATS 10240   // 40 KB static shared

// ---------------------------------------------------------------------------
// Core: 128x128 CTA tile, BK=16, 8 warps of 64x32, reg-prefetch double buffer.
// BN = true : B in gmem is [k][n], n contiguous (W, V) -> smem [k][n]
// BN = false: B in gmem is [n][k], k contiguous (K for NT scores) -> smem [n][k]
// ---------------------------------------------------------------------------
template <bool BN>
__device__ __forceinline__ void gemm_mma(float* sm, const float* Ag, size_t lda,
                                         const float* Bg, size_t ldb, int KT,
                                         float acc[4][4][4]) {
    const int tid = threadIdx.x;
    const int warp = tid >> 5, lane = tid & 31;
    const int g = lane >> 2, t = lane & 3;
    const int wm = (warp >> 2) << 6;   // 0 or 64
    const int wn = (warp & 3) << 5;    // 0,32,64,96

    float4 ra[2], rb[2];

#define LOADG(j)                                                              \
    do {                                                                      \
        _Pragma("unroll") for (int i = 0; i < 2; i++) {                       \
            int lin = tid + (i << 8);                                         \
            int ar = lin >> 2, ac = (lin & 3) << 2;                           \
            ra[i] = *(const float4*)(Ag + (size_t)ar * lda + (j) * 16 + ac);  \
            if (BN) {                                                         \
                int br = lin >> 5, bc = (lin & 31) << 2;                      \
                rb[i] = *(const float4*)(Bg + (size_t)((j) * 16 + br) * ldb + bc); \
            } else {                                                          \
                int br = lin >> 2, bc = (lin & 3) << 2;                       \
                rb[i] = *(const float4*)(Bg + (size_t)br * ldb + (j) * 16 + bc); \
            }                                                                 \
        }                                                                     \
    } while (0)

#define STORES(buf)                                                           \
    do {                                                                      \
        float* As = sm + ((buf) ? OFF_A1 : OFF_A0);                           \
        float* Bs = sm + ((buf) ? OFF_B1 : OFF_B0);                           \
        _Pragma("unroll") for (int i = 0; i < 2; i++) {                       \
            int lin = tid + (i << 8);                                         \
            int ar = lin >> 2, ac = (lin & 3) << 2;                           \
            float4 va = make_float4(to_tf32(ra[i].x), to_tf32(ra[i].y),       \
                                    to_tf32(ra[i].z), to_tf32(ra[i].w));      \
            *(float4*)(As + ar * STA + ac) = va;                              \
            float4 vb = make_float4(to_tf32(rb[i].x), to_tf32(rb[i].y),       \
                                    to_tf32(rb[i].z), to_tf32(rb[i].w));      \
            if (BN) {                                                         \
                int br = lin >> 5, bc = (lin & 31) << 2;                      \
                *(float4*)(Bs + br * STBN + bc) = vb;                         \
            } else {                                                          \
                int br = lin >> 2, bc = (lin & 3) << 2;                       \
                *(float4*)(Bs + br * STA + bc) = vb;                          \
            }                                                                 \
        }                                                                     \
    } while (0)

    LOADG(0);
    STORES(0);
    __syncthreads();

    for (int j = 0; j < KT; ++j) {
        const int buf = j & 1;
        if (j + 1 < KT) LOADG(j + 1);

        const float* As = sm + (buf ? OFF_A1 : OFF_A0);
        const float* Bs = sm + (buf ? OFF_B1 : OFF_B0);

#pragma unroll
        for (int kk = 0; kk < 2; ++kk) {
            const int k8 = kk << 3;
            uint32_t af[4][4], bf[4][2];
#pragma unroll
            for (int im = 0; im < 4; im++) {
                const float* ap = As + (wm + (im << 4)) * STA + k8;
                af[im][0] = __float_as_uint(ap[g * STA + t]);
                af[im][1] = __float_as_uint(ap[(g + 8) * STA + t]);
                af[im][2] = __float_as_uint(ap[g * STA + t + 4]);
                af[im][3] = __float_as_uint(ap[(g + 8) * STA + t + 4]);
            }
#pragma unroll
            for (int in = 0; in < 4; in++) {
                if (BN) {
                    const float* bp = Bs + (k8 + t) * STBN + wn + (in << 3) + g;
                    bf[in][0] = __float_as_uint(bp[0]);
                    bf[in][1] = __float_as_uint(bp[4 * STBN]);
                } else {
                    const float* bp = Bs + (wn + (in << 3) + g) * STA + k8 + t;
                    bf[in][0] = __float_as_uint(bp[0]);
                    bf[in][1] = __float_as_uint(bp[4]);
                }
            }
#pragma unroll
            for (int im = 0; im < 4; im++)
#pragma unroll
                for (int in = 0; in < 4; in++) MMA_TF32(acc[im][in], af[im], bf[in]);
        }

        if (j + 1 < KT) STORES(buf ^ 1);
        __syncthreads();
    }
#undef LOADG
#undef STORES
}

// Epilogue: write 128x128 tile. bias pre-offset to n0 (or null). out pre-offset
// to (m0, n0).
__device__ __forceinline__ void epilogue(float acc[4][4][4], float* out, size_t ld,
                                         const float* bias, float scale) {
    const int lane = threadIdx.x & 31, warp = threadIdx.x >> 5;
    const int g = lane >> 2, t = lane & 3;
    const int wm = (warp >> 2) << 6, wn = (warp & 3) << 5;
#pragma unroll
    for (int im = 0; im < 4; im++) {
#pragma unroll
        for (int in = 0; in < 4; in++) {
            const int r0 = wm + (im << 4) + g;
            const int c = wn + (in << 3) + (t << 1);
            float b0 = bias ? bias[c] : 0.f;
            float b1 = bias ? bias[c + 1] : 0.f;
            float2 v0 = make_float2(acc[im][in][0] * scale + b0,
                                    acc[im][in][1] * scale + b1);
            float2 v1 = make_float2(acc[im][in][2] * scale + b0,
                                    acc[im][in][3] * scale + b1);
            *(float2*)(out + (size_t)r0 * ld + c) = v0;
            *(float2*)(out + (size_t)(r0 + 8) * ld + c) = v1;
        }
    }
}

#define ZERO_ACC(acc)                                                         \
    _Pragma("unroll") for (int i = 0; i < 4; i++)                             \
    _Pragma("unroll") for (int j = 0; j < 4; j++)                             \
    _Pragma("unroll") for (int k = 0; k < 4; k++) (acc)[i][j][k] = 0.f

// ---------------------------------------------------------------------------
// Kernel 1: QKV projection  C = A @ W + b   (W is [K,N] row-major -> BN path)
// ---------------------------------------------------------------------------
__global__ __launch_bounds__(256, 2) void qkv_mma_kernel(
    const float* __restrict__ q_in, const float* __restrict__ k_in,
    const float* __restrict__ v_in,
    const float* __restrict__ Wq, const float* __restrict__ bq,
    const float* __restrict__ Wk, const float* __restrict__ bk,
    const float* __restrict__ Wv, const float* __restrict__ bv)
{
    __shared__ float sm[SM_FLOATS];
    const int which = blockIdx.z;
    const float* A    = (which == 0) ? q_in : (which == 1) ? k_in : v_in;
    const float* W    = (which == 0) ? Wq   : (which == 1) ? Wk   : Wv;
    const float* bias = (which == 0) ? bq   : (which == 1) ? bk   : bv;
    float* C          = (which == 0) ? g_q  : (which == 1) ? g_k  : g_v;

    const int m0 = blockIdx.y << 7, n0 = blockIdx.x << 7;
    float acc[4][4][4];
    ZERO_ACC(acc);
    gemm_mma<true>(sm, A + (size_t)m0 * D_, D_, W + n0, D_, D_ / 16, acc);
    epilogue(acc, C + (size_t)m0 * D_ + n0, D_, bias + n0, 1.0f);
}

// ---------------------------------------------------------------------------
// Kernel 2: scores = (Q @ K^T)/32, lower-triangular blocks only (NT -> BT path)
// ---------------------------------------------------------------------------
__global__ __launch_bounds__(256, 2) void scores_mma_kernel()
{
    const int bn = blockIdx.x, bm = blockIdx.y, b = blockIdx.z;
    if (bn > bm) return;
    __shared__ float sm[SM_FLOATS];
    const int m0 = bm << 7, n0 = bn << 7;
    const float* Qb = g_q + (size_t)b * S_ * D_;
    const float* Kb = g_k + (size_t)b * S_ * D_;

    float acc[4][4][4];
    ZERO_ACC(acc);
    gemm_mma<false>(sm, Qb + (size_t)m0 * D_, D_, Kb + (size_t)n0 * D_, D_,
                    D_ / 16, acc);
    epilogue(acc, g_p + (size_t)b * S_ * S_ + (size_t)m0 * S_ + n0, S_,
             nullptr, 0.03125f);
}

// ---------------------------------------------------------------------------
// Kernel 3: causal row softmax; zero-pads [L, Lpad) for the AV GEMM
// ---------------------------------------------------------------------------
__global__ __launch_bounds__(256) void softmax_kernel()
{
    const int m = blockIdx.x;
    const int b = blockIdx.y;
    float* row = g_p + ((size_t)b * S_ + m) * S_;
    const int L = m + 1;
    const int Lpad = ((m >> 7) + 1) << 7;

    __shared__ float smx[S_];
    __shared__ float red[256];
    const int tid = threadIdx.x;

    float mx = -INFINITY;
    for (int i = tid; i < L; i += 256) {
        float v = row[i];
        smx[i] = v;
        mx = fmaxf(mx, v);
    }
    red[tid] = mx;
    __syncthreads();
    for (int s = 128; s > 0; s >>= 1) {
        if (tid < s) red[tid] = fmaxf(red[tid], red[tid + s]);
        __syncthreads();
    }
    mx = red[0];
    __syncthreads();

    float sum = 0.f;
    for (int i = tid; i < L; i += 256) {
        float e = __expf(smx[i] - mx);
        smx[i] = e;
        sum += e;
    }
    red[tid] = sum;
    __syncthreads();
    for (int s = 128; s > 0; s >>= 1) {
        if (tid < s) red[tid] += red[tid + s];
        __syncthreads();
    }
    const float inv = 1.f / red[0];
    __syncthreads();

    for (int i = tid; i < Lpad; i += 256)
        row[i] = (i < L) ? smx[i] * inv : 0.f;
}

// ---------------------------------------------------------------------------
// Kernel 4: out = P @ V  (V [K,N] row-major -> BN path), causal K truncation
// ---------------------------------------------------------------------------
__global__ __launch_bounds__(256, 2) void av_mma_kernel(float* __restrict__ out)
{
    __shared__ float sm[SM_FLOATS];
    const int bn = blockIdx.x, bm = blockIdx.y, b = blockIdx.z;
    const int m0 = bm << 7, n0 = bn << 7;

    const float* Pb = g_p + (size_t)b * S_ * S_;
    const float* Vb = g_v + (size_t)b * S_ * D_;

    float acc[4][4][4];
    ZERO_ACC(acc);
    gemm_mma<true>(sm, Pb + (size_t)m0 * S_, S_, Vb + n0, D_, (bm + 1) * 8, acc);
    epilogue(acc, out + (size_t)b * S_ * D_ + (size_t)m0 * D_ + n0, D_,
             nullptr, 1.0f);
}

// ---------------------------------------------------------------------------
extern "C" void kernel_launch(void* const* d_in, const int* in_sizes, int n_in,
                              void* d_out, int out_size)
{
    const float* query = (const float*)d_in[0];
    const float* key   = (const float*)d_in[1];
    const float* value = (const float*)d_in[2];
    // d_in[3] = causal mask (static; unused)
    const float* Wq = (const float*)d_in[4];
    const float* bq = (const float*)d_in[5];
    const float* Wk = (const float*)d_in[6];
    const float* bk = (const float*)d_in[7];
    const float* Wv = (const float*)d_in[8];
    const float* bv = (const float*)d_in[9];
    float* out = (float*)d_out;

    dim3 block(256);

    qkv_mma_kernel<<<dim3(D_ / 128, NROWS / 128, 3), block>>>(
        query, key, value, Wq, bq, Wk, bk, Wv, bv);

    scores_mma_kernel<<<dim3(S_ / 128, S_ / 128, B_), block>>>();

    softmax_kernel<<<dim3(S_, B_), block>>>();

    av_mma_kernel<<<dim3(D_ / 128, S_ / 128, B_), block>>>(out);
}

// round 4
// speedup vs baseline: 3.0079x; 1.0366x over previous
#include <cuda_runtime.h>
#include <math.h>
#include <stdint.h>

#define B_ 8
#define S_ 2048
#define D_ 1024
#define NROWS (B_ * S_)
#define BK 16
#define NSTAGE 5
#define STA 20                       // floats per SMEM row (80B): ldmatrix conflict-free
#define TILE_FLOATS (128 * STA)      // 2560 floats = 10240 B per operand tile
#define TILE_BYTES (TILE_FLOATS * 4)
#define SM_BYTES (NSTAGE * 2 * TILE_BYTES)   // 102400 B dynamic smem

// Scratch (device globals: allowed; no runtime allocation)
__device__ float g_q[(size_t)NROWS * D_];          // [b][s][d]
__device__ float g_k[(size_t)NROWS * D_];          // [b][s][d]
__device__ float g_v[(size_t)NROWS * D_];          // TRANSPOSED: [b][d][s]
__device__ float g_p[(size_t)B_ * S_ * S_];        // [b][s_q][s_k]
__device__ float g_wt[3 * (size_t)D_ * D_];        // W^T: [which][n][k]

// ---------------------------------------------------------------------------
// PTX helpers (base ISA only: cp.async / ldmatrix / mma.sync — no tcgen05)
// ---------------------------------------------------------------------------
__device__ __forceinline__ uint32_t smem_u32(const void* p) {
    uint32_t a;
    asm("{ .reg .u64 t; cvta.to.shared.u64 t, %1; cvt.u32.u64 %0, t; }"
        : "=r"(a) : "l"(p));
    return a;
}

#define CP16(dst, src)                                                        \
    asm volatile("cp.async.cg.shared.global [%0], [%1], 16;"                  \
                 :: "r"(dst), "l"(src))
#define CP_COMMIT() asm volatile("cp.async.commit_group;" ::: "memory")
#define CP_WAIT3()  asm volatile("cp.async.wait_group 3;" ::: "memory")

#define LDMX4(r0, r1, r2, r3, addr)                                           \
    asm volatile("ldmatrix.sync.aligned.m8n8.x4.shared.b16 {%0,%1,%2,%3}, [%4];" \
                 : "=r"(r0), "=r"(r1), "=r"(r2), "=r"(r3) : "r"(addr))

#define CVT_TF32(u) asm volatile("cvt.rna.tf32.f32 %0, %1;" : "=r"(u) : "r"(u))

#define MMA_TF32(c, a, b)                                                     \
    asm volatile(                                                             \
        "mma.sync.aligned.m16n8k8.row.col.f32.tf32.tf32.f32 "                 \
        "{%0,%1,%2,%3}, {%4,%5,%6,%7}, {%8,%9}, {%0,%1,%2,%3};"               \
        : "+f"((c)[0]), "+f"((c)[1]), "+f"((c)[2]), "+f"((c)[3])              \
        : "r"((a)[0]), "r"((a)[1]), "r"((a)[2]), "r"((a)[3]),                 \
          "r"((b)[0]), "r"((b)[1]))

#define ZERO_ACC(acc)                                                         \
    _Pragma("unroll") for (int i = 0; i < 4; i++)                             \
    _Pragma("unroll") for (int j = 0; j < 4; j++)                             \
    _Pragma("unroll") for (int k = 0; k < 4; k++) (acc)[i][j][k] = 0.f

// ---------------------------------------------------------------------------
// cp.async one chunk: A tile 128x16 + B tile 128x16 (both [row][k] in gmem).
// 4 x 16B per thread; dst rows at 80B stride (64B data + 16B pad).
// ---------------------------------------------------------------------------
__device__ __forceinline__ void issue_tile(uint32_t smA, const float* Ag, size_t lda,
                                           uint32_t smB, const float* Bg, size_t ldb,
                                           int j, int tid) {
#pragma unroll
    for (int w = 0; w < 2; w++) {
        const int lin = tid + (w << 8);
        const int r = lin >> 2, s4 = (lin & 3) << 2;
        CP16(smA + r * 80 + (s4 << 2), Ag + (size_t)r * lda + j * BK + s4);
        CP16(smB + r * 80 + (s4 << 2), Bg + (size_t)r * ldb + j * BK + s4);
    }
}

// ---------------------------------------------------------------------------
// Compute one K=16 chunk from SMEM via ldmatrix.x4 + cvt.rna + mma.
// ---------------------------------------------------------------------------
__device__ __forceinline__ void compute_tile(uint32_t smA, uint32_t smB,
                                             int wm, int wn, int lane,
                                             float acc[4][4][4]) {
    const int a_row = lane & 15;                  // A: +row within 16
    const int a_col = ((lane >> 4) & 1) << 2;     // A: k half select
    const int b_row = (lane & 7) + (((lane >> 4) & 1) << 3);  // B: row + in-pair sel
    const int b_col = ((lane >> 3) & 1) << 2;     // B: k half select

#pragma unroll
    for (int k8 = 0; k8 < 16; k8 += 8) {
        uint32_t af[4][4];
#pragma unroll
        for (int im = 0; im < 4; im++) {
            uint32_t addr = smA + (uint32_t)(((wm + (im << 4) + a_row) * STA + k8 + a_col) << 2);
            LDMX4(af[im][0], af[im][1], af[im][2], af[im][3], addr);
        }
        uint32_t bf[4][2];
#pragma unroll
        for (int ip = 0; ip < 2; ip++) {
            uint32_t addr = smB + (uint32_t)(((wn + (ip << 4) + b_row) * STA + k8 + b_col) << 2);
            LDMX4(bf[2 * ip][0], bf[2 * ip][1], bf[2 * ip + 1][0], bf[2 * ip + 1][1], addr);
        }
#pragma unroll
        for (int im = 0; im < 4; im++) {
            CVT_TF32(af[im][0]); CVT_TF32(af[im][1]);
            CVT_TF32(af[im][2]); CVT_TF32(af[im][3]);
        }
#pragma unroll
        for (int in = 0; in < 4; in++) { CVT_TF32(bf[in][0]); CVT_TF32(bf[in][1]); }
#pragma unroll
        for (int im = 0; im < 4; im++)
#pragma unroll
            for (int in = 0; in < 4; in++) MMA_TF32(acc[im][in], af[im], bf[in]);
    }
}

// ---------------------------------------------------------------------------
// 5-stage cp.async pipelined mainloop. A and B both [row][k] gmem layout.
// ---------------------------------------------------------------------------
__device__ __forceinline__ void gemm_cp(const float* Ag, size_t lda,
                                        const float* Bg, size_t ldb, int KT,
                                        float acc[4][4][4]) {
    extern __shared__ float smf[];
    const int tid = threadIdx.x, lane = tid & 31, warp = tid >> 5;
    const int wm = (warp >> 2) << 6, wn = (warp & 3) << 5;
    const uint32_t smb = smem_u32(smf);

#pragma unroll
    for (int s = 0; s < 4; s++) {
        if (s < KT)
            issue_tile(smb + s * 2 * TILE_BYTES, Ag, lda,
                       smb + s * 2 * TILE_BYTES + TILE_BYTES, Bg, ldb, s, tid);
        CP_COMMIT();
    }
    for (int j = 0; j < KT; ++j) {
        CP_WAIT3();
        __syncthreads();
        const int jn = j + 4;
        if (jn < KT) {
            const int bs = jn % NSTAGE;
            issue_tile(smb + bs * 2 * TILE_BYTES, Ag, lda,
                       smb + bs * 2 * TILE_BYTES + TILE_BYTES, Bg, ldb, jn, tid);
        }
        CP_COMMIT();
        const int cs = j % NSTAGE;
        compute_tile(smb + cs * 2 * TILE_BYTES,
                     smb + cs * 2 * TILE_BYTES + TILE_BYTES, wm, wn, lane, acc);
    }
}

// ---------------------------------------------------------------------------
// Epilogues
// ---------------------------------------------------------------------------
__device__ __forceinline__ void epilogue(float acc[4][4][4], float* out, size_t ld,
                                         const float* bias, float scale) {
    const int lane = threadIdx.x & 31, warp = threadIdx.x >> 5;
    const int g = lane >> 2, t = lane & 3;
    const int wm = (warp >> 2) << 6, wn = (warp & 3) << 5;
#pragma unroll
    for (int im = 0; im < 4; im++) {
#pragma unroll
        for (int in = 0; in < 4; in++) {
            const int r0 = wm + (im << 4) + g;
            const int c = wn + (in << 3) + (t << 1);
            float b0 = bias ? bias[c] : 0.f;
            float b1 = bias ? bias[c + 1] : 0.f;
            float2 v0 = make_float2(acc[im][in][0] * scale + b0,
                                    acc[im][in][1] * scale + b1);
            float2 v1 = make_float2(acc[im][in][2] * scale + b0,
                                    acc[im][in][3] * scale + b1);
            *(float2*)(out + (size_t)r0 * ld + c) = v0;
            *(float2*)(out + (size_t)(r0 + 8) * ld + c) = v1;
        }
    }
}

// Transposed store for V: vt is [D][S] for this batch; quad lanes fill full
// 32B sectors (8 consecutive seq rows per column) so scatter stays efficient.
__device__ __forceinline__ void epilogue_vt(float acc[4][4][4], float* vt,
                                            int mloc, int n0, const float* bias) {
    const int lane = threadIdx.x & 31, warp = threadIdx.x >> 5;
    const int g = lane >> 2, t = lane & 3;
    const int wm = (warp >> 2) << 6, wn = (warp & 3) << 5;
#pragma unroll
    for (int im = 0; im < 4; im++) {
#pragma unroll
        for (int in = 0; in < 4; in++) {
            const int r = mloc + wm + (im << 4) + g;
            const int c = n0 + wn + (in << 3) + (t << 1);
            const float b0 = bias[c], b1 = bias[c + 1];
            vt[(size_t)c * S_ + r]           = acc[im][in][0] + b0;
            vt[(size_t)(c + 1) * S_ + r]     = acc[im][in][1] + b1;
            vt[(size_t)c * S_ + r + 8]       = acc[im][in][2] + b0;
            vt[(size_t)(c + 1) * S_ + r + 8] = acc[im][in][3] + b1;
        }
    }
}

// ---------------------------------------------------------------------------
// Kernel 0: transpose W -> g_wt  ([k][n] -> [n][k])
// ---------------------------------------------------------------------------
__global__ __launch_bounds__(256) void wt_kernel(const float* __restrict__ Wq,
                                                 const float* __restrict__ Wk,
                                                 const float* __restrict__ Wv) {
    const int z = blockIdx.z;
    const float* W = (z == 0) ? Wq : (z == 1) ? Wk : Wv;
    float* WT = g_wt + (size_t)z * D_ * D_;
    __shared__ float t[32][33];
    const int tx = threadIdx.x & 31, ty = threadIdx.x >> 5;
    const int x0 = blockIdx.x << 5, y0 = blockIdx.y << 5;
#pragma unroll
    for (int i = 0; i < 4; i++)
        t[ty + i * 8][tx] = W[(size_t)(y0 + ty + i * 8) * D_ + x0 + tx];
    __syncthreads();
#pragma unroll
    for (int i = 0; i < 4; i++)
        WT[(size_t)(x0 + ty + i * 8) * D_ + y0 + tx] = t[tx][ty + i * 8];
}

// ---------------------------------------------------------------------------
// Kernel 1: QKV projection  C = A @ W + b   (B side = W^T rows, k contiguous)
// ---------------------------------------------------------------------------
__global__ __launch_bounds__(256, 2) void qkv_mma_kernel(
    const float* __restrict__ q_in, const float* __restrict__ k_in,
    const float* __restrict__ v_in,
    const float* __restrict__ bq, const float* __restrict__ bk,
    const float* __restrict__ bv)
{
    const int which = blockIdx.z;
    const float* A    = (which == 0) ? q_in : (which == 1) ? k_in : v_in;
    const float* bias = (which == 0) ? bq   : (which == 1) ? bk   : bv;

    const int m0 = blockIdx.y << 7, n0 = blockIdx.x << 7;
    float acc[4][4][4];
    ZERO_ACC(acc);
    gemm_cp(A + (size_t)m0 * D_, D_,
            g_wt + (size_t)which * D_ * D_ + (size_t)n0 * D_, D_, D_ / BK, acc);

    if (which == 2) {
        const int b = m0 >> 11;
        epilogue_vt(acc, g_v + (size_t)b * D_ * S_, m0 & (S_ - 1), n0, bias);
    } else {
        float* C = (which == 0) ? g_q : g_k;
        epilogue(acc, C + (size_t)m0 * D_ + n0, D_, bias + n0, 1.0f);
    }
}

// ---------------------------------------------------------------------------
// Kernel 2: scores = (Q @ K^T)/32, lower-triangular blocks only
// ---------------------------------------------------------------------------
__global__ __launch_bounds__(256, 2) void scores_mma_kernel()
{
    const int bn = blockIdx.x, bm = blockIdx.y, b = blockIdx.z;
    if (bn > bm) return;
    const int m0 = bm << 7, n0 = bn << 7;

    float acc[4][4][4];
    ZERO_ACC(acc);
    gemm_cp(g_q + (size_t)b * S_ * D_ + (size_t)m0 * D_, D_,
            g_k + (size_t)b * S_ * D_ + (size_t)n0 * D_, D_, D_ / BK, acc);
    epilogue(acc, g_p + (size_t)b * S_ * S_ + (size_t)m0 * S_ + n0, S_,
             nullptr, 0.03125f);
}

// ---------------------------------------------------------------------------
// Kernel 3: causal row softmax; zero-pads [L, Lpad) for the AV GEMM
// ---------------------------------------------------------------------------
__global__ __launch_bounds__(256) void softmax_kernel()
{
    const int m = blockIdx.x;
    const int b = blockIdx.y;
    float* row = g_p + ((size_t)b * S_ + m) * S_;
    const int L = m + 1;
    const int Lpad = ((m >> 7) + 1) << 7;

    __shared__ float smx[S_];
    __shared__ float red[256];
    const int tid = threadIdx.x;

    float mx = -INFINITY;
    for (int i = tid; i < L; i += 256) {
        float v = row[i];
        smx[i] = v;
        mx = fmaxf(mx, v);
    }
    red[tid] = mx;
    __syncthreads();
    for (int s = 128; s > 0; s >>= 1) {
        if (tid < s) red[tid] = fmaxf(red[tid], red[tid + s]);
        __syncthreads();
    }
    mx = red[0];
    __syncthreads();

    float sum = 0.f;
    for (int i = tid; i < L; i += 256) {
        float e = __expf(smx[i] - mx);
        smx[i] = e;
        sum += e;
    }
    red[tid] = sum;
    __syncthreads();
    for (int s = 128; s > 0; s >>= 1) {
        if (tid < s) red[tid] += red[tid + s];
        __syncthreads();
    }
    const float inv = 1.f / red[0];
    __syncthreads();

    for (int i = tid; i < Lpad; i += 256)
        row[i] = (i < L) ? smx[i] * inv : 0.f;
}

// ---------------------------------------------------------------------------
// Kernel 4: out = P @ V  (B side = V^T rows, seq contiguous), causal K trunc
// ---------------------------------------------------------------------------
__global__ __launch_bounds__(256, 2) void av_mma_kernel(float* __restrict__ out)
{
    const int bn = blockIdx.x, bm = blockIdx.y, b = blockIdx.z;
    const int m0 = bm << 7, n0 = bn << 7;

    float acc[4][4][4];
    ZERO_ACC(acc);
    gemm_cp(g_p + (size_t)b * S_ * S_ + (size_t)m0 * S_, S_,
            g_v + (size_t)b * D_ * S_ + (size_t)n0 * S_, S_, (bm + 1) * 8, acc);
    epilogue(acc, out + (size_t)b * S_ * D_ + (size_t)m0 * D_ + n0, D_,
             nullptr, 1.0f);
}

// ---------------------------------------------------------------------------
extern "C" void kernel_launch(void* const* d_in, const int* in_sizes, int n_in,
                              void* d_out, int out_size)
{
    const float* query = (const float*)d_in[0];
    const float* key   = (const float*)d_in[1];
    const float* value = (const float*)d_in[2];
    // d_in[3] = causal mask (static; unused)
    const float* Wq = (const float*)d_in[4];
    const float* bq = (const float*)d_in[5];
    const float* Wk = (const float*)d_in[6];
    const float* bk = (const float*)d_in[7];
    const float* Wv = (const float*)d_in[8];
    const float* bv = (const float*)d_in[9];
    float* out = (float*)d_out;

    static int attr_done = 0;
    if (!attr_done) {
        cudaFuncSetAttribute(qkv_mma_kernel,
                             cudaFuncAttributeMaxDynamicSharedMemorySize, SM_BYTES);
        cudaFuncSetAttribute(scores_mma_kernel,
                             cudaFuncAttributeMaxDynamicSharedMemorySize, SM_BYTES);
        cudaFuncSetAttribute(av_mma_kernel,
                             cudaFuncAttributeMaxDynamicSharedMemorySize, SM_BYTES);
        attr_done = 1;
    }

    dim3 block(256);

    wt_kernel<<<dim3(32, 32, 3), block>>>(Wq, Wk, Wv);

    qkv_mma_kernel<<<dim3(D_ / 128, NROWS / 128, 3), block, SM_BYTES>>>(
        query, key, value, bq, bk, bv);

    scores_mma_kernel<<<dim3(S_ / 128, S_ / 128, B_), block, SM_BYTES>>>();

    softmax_kernel<<<dim3(S_, B_), block>>>();

    av_mma_kernel<<<dim3(D_ / 128, S_ / 128, B_), block, SM_BYTES>>>(out);
}

// round 5
// speedup vs baseline: 5.7717x; 1.9188x over previous
#include <cuda_runtime.h>
#include <cuda_fp16.h>
#include <math.h>
#include <stdint.h>

#define B_ 8
#define S_ 2048
#define D_ 1024
#define NROWS (B_ * S_)
#define BKH 32                        // k-halves per chunk (64B per row)
#define NSTAGE 5
#define STA 40                        // halves per SMEM row (80B): ldmatrix conflict-free
#define TILE_BYTES (128 * 80)         // 10240 B per operand tile
#define SM_BYTES (NSTAGE * 2 * TILE_BYTES)   // 102400 B dynamic smem

// Scratch (device globals: allowed; no runtime allocation)
__device__ __half g_xq[(size_t)NROWS * D_];   // fp16 copy of query
__device__ __half g_xk[(size_t)NROWS * D_];   // fp16 copy of key
__device__ __half g_xv[(size_t)NROWS * D_];   // fp16 copy of value
__device__ __half g_q[(size_t)NROWS * D_];    // q proj [row][d]
__device__ __half g_k[(size_t)NROWS * D_];    // k proj [row][d]
__device__ __half g_v[(size_t)NROWS * D_];    // v proj TRANSPOSED [b][d][s]
__device__ __half g_p[(size_t)B_ * S_ * S_];  // scores -> probs [b][sq][sk]
__device__ __half g_wt[3 * (size_t)D_ * D_];  // W^T fp16 [which][n][k]

// ---------------------------------------------------------------------------
// PTX helpers (base ISA: cp.async / ldmatrix / mma.sync — no tcgen05)
// ---------------------------------------------------------------------------
__device__ __forceinline__ uint32_t smem_u32(const void* p) {
    uint32_t a;
    asm("{ .reg .u64 t; cvta.to.shared.u64 t, %1; cvt.u32.u64 %0, t; }"
        : "=r"(a) : "l"(p));
    return a;
}

#define CP16(dst, src)                                                        \
    asm volatile("cp.async.cg.shared.global [%0], [%1], 16;"                  \
                 :: "r"(dst), "l"(src))
#define CP_COMMIT() asm volatile("cp.async.commit_group;" ::: "memory")
#define CP_WAIT3()  asm volatile("cp.async.wait_group 3;" ::: "memory")

#define LDMX4(r0, r1, r2, r3, addr)                                           \
    asm volatile("ldmatrix.sync.aligned.m8n8.x4.shared.b16 {%0,%1,%2,%3}, [%4];" \
                 : "=r"(r0), "=r"(r1), "=r"(r2), "=r"(r3) : "r"(addr))

#define MMA_F16(c, a, b)                                                      \
    asm volatile(                                                             \
        "mma.sync.aligned.m16n8k16.row.col.f32.f16.f16.f32 "                  \
        "{%0,%1,%2,%3}, {%4,%5,%6,%7}, {%8,%9}, {%0,%1,%2,%3};"               \
        : "+f"((c)[0]), "+f"((c)[1]), "+f"((c)[2]), "+f"((c)[3])              \
        : "r"((a)[0]), "r"((a)[1]), "r"((a)[2]), "r"((a)[3]),                 \
          "r"((b)[0]), "r"((b)[1]))

#define ZERO_ACC(acc)                                                         \
    _Pragma("unroll") for (int i = 0; i < 4; i++)                             \
    _Pragma("unroll") for (int j = 0; j < 4; j++)                             \
    _Pragma("unroll") for (int k = 0; k < 4; k++) (acc)[i][j][k] = 0.f

// ---------------------------------------------------------------------------
// cp.async one chunk: A tile 128x32h + B tile 128x32h (both [row][k] fp16).
// 4 x 16B per thread total; dst rows 80B stride (64B data + 16B pad).
// ---------------------------------------------------------------------------
__device__ __forceinline__ void issue_tile(uint32_t smA, const __half* Ag, size_t lda,
                                           uint32_t smB, const __half* Bg, size_t ldb,
                                           int j, int tid) {
#pragma unroll
    for (int w = 0; w < 2; w++) {
        const int lin = tid + (w << 8);          // 0..511
        const int r = lin >> 2, q = lin & 3;
        CP16(smA + r * 80 + (q << 4), Ag + (size_t)r * lda + j * BKH + (q << 3));
        CP16(smB + r * 80 + (q << 4), Bg + (size_t)r * ldb + j * BKH + (q << 3));
    }
}

// ---------------------------------------------------------------------------
// Compute one K=32h chunk: 2 sub-k of 16; ldmatrix.x4 native b16 + mma k16.
// ---------------------------------------------------------------------------
__device__ __forceinline__ void compute_tile(uint32_t smA, uint32_t smB,
                                             int wm, int wn, int lane,
                                             float acc[4][4][4]) {
    const int a_row = lane & 15;
    const int a_k8  = ((lane >> 4) & 1) << 3;
    const int b_row = (lane & 7) + (((lane >> 4) & 1) << 3);
    const int b_k8  = ((lane >> 3) & 1) << 3;

#pragma unroll
    for (int k16 = 0; k16 < BKH; k16 += 16) {
        uint32_t af[4][4];
#pragma unroll
        for (int im = 0; im < 4; im++) {
            uint32_t addr = smA +
                (uint32_t)(((wm + (im << 4) + a_row) * STA + k16 + a_k8) << 1);
            LDMX4(af[im][0], af[im][1], af[im][2], af[im][3], addr);
        }
        uint32_t bf[4][2];
#pragma unroll
        for (int ip = 0; ip < 2; ip++) {
            uint32_t addr = smB +
                (uint32_t)(((wn + (ip << 4) + b_row) * STA + k16 + b_k8) << 1);
            LDMX4(bf[2 * ip][0], bf[2 * ip][1], bf[2 * ip + 1][0], bf[2 * ip + 1][1], addr);
        }
#pragma unroll
        for (int im = 0; im < 4; im++)
#pragma unroll
            for (int in = 0; in < 4; in++) MMA_F16(acc[im][in], af[im], bf[in]);
    }
}

// ---------------------------------------------------------------------------
// 5-stage cp.async pipelined mainloop. A and B both [row][k] fp16.
// ---------------------------------------------------------------------------
__device__ __forceinline__ void gemm_cp(const __half* Ag, size_t lda,
                                        const __half* Bg, size_t ldb, int KT,
                                        float acc[4][4][4]) {
    extern __shared__ __half smh[];
    const int tid = threadIdx.x, lane = tid & 31, warp = tid >> 5;
    const int wm = (warp >> 2) << 6, wn = (warp & 3) << 5;
    const uint32_t smb = smem_u32(smh);

#pragma unroll
    for (int s = 0; s < 4; s++) {
        if (s < KT)
            issue_tile(smb + s * 2 * TILE_BYTES, Ag, lda,
                       smb + s * 2 * TILE_BYTES + TILE_BYTES, Bg, ldb, s, tid);
        CP_COMMIT();
    }
    for (int j = 0; j < KT; ++j) {
        CP_WAIT3();
        __syncthreads();
        const int jn = j + 4;
        if (jn < KT) {
            const int bs = jn % NSTAGE;
            issue_tile(smb + bs * 2 * TILE_BYTES, Ag, lda,
                       smb + bs * 2 * TILE_BYTES + TILE_BYTES, Bg, ldb, jn, tid);
        }
        CP_COMMIT();
        const int cs = j % NSTAGE;
        compute_tile(smb + cs * 2 * TILE_BYTES,
                     smb + cs * 2 * TILE_BYTES + TILE_BYTES, wm, wn, lane, acc);
    }
}

// ---------------------------------------------------------------------------
// Epilogues (acc frag: c0,c1 @ row g cols 2t,2t+1; c2,c3 @ row g+8)
// ---------------------------------------------------------------------------
__device__ __forceinline__ void epilogue_h(float acc[4][4][4], __half* out, size_t ld,
                                           const float* bias, float scale) {
    const int lane = threadIdx.x & 31, warp = threadIdx.x >> 5;
    const int g = lane >> 2, t = lane & 3;
    const int wm = (warp >> 2) << 6, wn = (warp & 3) << 5;
#pragma unroll
    for (int im = 0; im < 4; im++) {
#pragma unroll
        for (int in = 0; in < 4; in++) {
            const int r0 = wm + (im << 4) + g;
            const int c = wn + (in << 3) + (t << 1);
            const float b0 = bias ? bias[c] : 0.f;
            const float b1 = bias ? bias[c + 1] : 0.f;
            *(__half2*)(out + (size_t)r0 * ld + c) =
                __floats2half2_rn(acc[im][in][0] * scale + b0,
                                  acc[im][in][1] * scale + b1);
            *(__half2*)(out + (size_t)(r0 + 8) * ld + c) =
                __floats2half2_rn(acc[im][in][2] * scale + b0,
                                  acc[im][in][3] * scale + b1);
        }
    }
}

__device__ __forceinline__ void epilogue_f(float acc[4][4][4], float* out, size_t ld) {
    const int lane = threadIdx.x & 31, warp = threadIdx.x >> 5;
    const int g = lane >> 2, t = lane & 3;
    const int wm = (warp >> 2) << 6, wn = (warp & 3) << 5;
#pragma unroll
    for (int im = 0; im < 4; im++) {
#pragma unroll
        for (int in = 0; in < 4; in++) {
            const int r0 = wm + (im << 4) + g;
            const int c = wn + (in << 3) + (t << 1);
            *(float2*)(out + (size_t)r0 * ld + c) =
                make_float2(acc[im][in][0], acc[im][in][1]);
            *(float2*)(out + (size_t)(r0 + 8) * ld + c) =
                make_float2(acc[im][in][2], acc[im][in][3]);
        }
    }
}

// Transposed store for V: vt is [D][S] for this batch (fp16).
__device__ __forceinline__ void epilogue_vt(float acc[4][4][4], __half* vt,
                                            int mloc, int n0, const float* bias) {
    const int lane = threadIdx.x & 31, warp = threadIdx.x >> 5;
    const int g = lane >> 2, t = lane & 3;
    const int wm = (warp >> 2) << 6, wn = (warp & 3) << 5;
#pragma unroll
    for (int im = 0; im < 4; im++) {
#pragma unroll
        for (int in = 0; in < 4; in++) {
            const int r = mloc + wm + (im << 4) + g;
            const int c = n0 + wn + (in << 3) + (t << 1);
            const float b0 = bias[c], b1 = bias[c + 1];
            vt[(size_t)c * S_ + r]           = __float2half_rn(acc[im][in][0] + b0);
            vt[(size_t)(c + 1) * S_ + r]     = __float2half_rn(acc[im][in][1] + b1);
            vt[(size_t)c * S_ + r + 8]       = __float2half_rn(acc[im][in][2] + b0);
            vt[(size_t)(c + 1) * S_ + r + 8] = __float2half_rn(acc[im][in][3] + b1);
        }
    }
}

// ---------------------------------------------------------------------------
// Kernel 0a: fp32 -> fp16 convert of raw query/key/value
// ---------------------------------------------------------------------------
__global__ __launch_bounds__(256) void cvt_inputs_kernel(
    const float* __restrict__ q, const float* __restrict__ k,
    const float* __restrict__ v) {
    const int z = blockIdx.z;
    const float* src = (z == 0) ? q : (z == 1) ? k : v;
    __half* dst = (z == 0) ? g_xq : (z == 1) ? g_xk : g_xv;
    const size_t i = ((size_t)blockIdx.x * 256 + threadIdx.x) * 4;
    float4 f = *(const float4*)(src + i);
    __half2* d2 = (__half2*)(dst + i);
    d2[0] = __floats2half2_rn(f.x, f.y);
    d2[1] = __floats2half2_rn(f.z, f.w);
}

// ---------------------------------------------------------------------------
// Kernel 0b: W ([k][n] fp32) -> g_wt ([n][k] fp16)
// ---------------------------------------------------------------------------
__global__ __launch_bounds__(256) void wt_kernel(const float* __restrict__ Wq,
                                                 const float* __restrict__ Wk,
                                                 const float* __restrict__ Wv) {
    const int z = blockIdx.z;
    const float* W = (z == 0) ? Wq : (z == 1) ? Wk : Wv;
    __half* WT = g_wt + (size_t)z * D_ * D_;
    __shared__ float t[32][33];
    const int tx = threadIdx.x & 31, ty = threadIdx.x >> 5;
    const int x0 = blockIdx.x << 5, y0 = blockIdx.y << 5;
#pragma unroll
    for (int i = 0; i < 4; i++)
        t[ty + i * 8][tx] = W[(size_t)(y0 + ty + i * 8) * D_ + x0 + tx];
    __syncthreads();
#pragma unroll
    for (int i = 0; i < 4; i++)
        WT[(size_t)(x0 + ty + i * 8) * D_ + y0 + tx] = __float2half_rn(t[tx][ty + i * 8]);
}

// ---------------------------------------------------------------------------
// Kernel 1: QKV projection  C = X @ W + b
// ---------------------------------------------------------------------------
__global__ __launch_bounds__(256, 2) void qkv_mma_kernel(
    const float* __restrict__ bq, const float* __restrict__ bk,
    const float* __restrict__ bv)
{
    const int which = blockIdx.z;
    const __half* A   = (which == 0) ? g_xq : (which == 1) ? g_xk : g_xv;
    const float* bias = (which == 0) ? bq   : (which == 1) ? bk   : bv;

    const int m0 = blockIdx.y << 7, n0 = blockIdx.x << 7;
    float acc[4][4][4];
    ZERO_ACC(acc);
    gemm_cp(A + (size_t)m0 * D_, D_,
            g_wt + (size_t)which * D_ * D_ + (size_t)n0 * D_, D_, D_ / BKH, acc);

    if (which == 2) {
        const int b = m0 >> 11;
        epilogue_vt(acc, g_v + (size_t)b * D_ * S_, m0 & (S_ - 1), n0, bias);
    } else {
        __half* C = (which == 0) ? g_q : g_k;
        epilogue_h(acc, C + (size_t)m0 * D_ + n0, D_, bias + n0, 1.0f);
    }
}

// ---------------------------------------------------------------------------
// Kernel 2: scores = (Q @ K^T)/32, lower-triangular blocks only
// ---------------------------------------------------------------------------
__global__ __launch_bounds__(256, 2) void scores_mma_kernel()
{
    const int bn = blockIdx.x, bm = blockIdx.y, b = blockIdx.z;
    if (bn > bm) return;
    const int m0 = bm << 7, n0 = bn << 7;

    float acc[4][4][4];
    ZERO_ACC(acc);
    gemm_cp(g_q + (size_t)b * S_ * D_ + (size_t)m0 * D_, D_,
            g_k + (size_t)b * S_ * D_ + (size_t)n0 * D_, D_, D_ / BKH, acc);
    epilogue_h(acc, g_p + (size_t)b * S_ * S_ + (size_t)m0 * S_ + n0, S_,
               nullptr, 0.03125f);
}

// ---------------------------------------------------------------------------
// Kernel 3: causal row softmax on fp16 P; zero-pads [L, Lpad)
// ---------------------------------------------------------------------------
__global__ __launch_bounds__(256) void softmax_kernel()
{
    const int m = blockIdx.x;
    const int b = blockIdx.y;
    __half* row = g_p + ((size_t)b * S_ + m) * S_;
    const int L = m + 1;
    const int Lpad = ((m >> 7) + 1) << 7;

    __shared__ float smx[S_];
    __shared__ float red[256];
    const int tid = threadIdx.x;

    float mx = -INFINITY;
    for (int i = tid; i < L; i += 256) {
        float v = __half2float(row[i]);
        smx[i] = v;
        mx = fmaxf(mx, v);
    }
    red[tid] = mx;
    __syncthreads();
    for (int s = 128; s > 0; s >>= 1) {
        if (tid < s) red[tid] = fmaxf(red[tid], red[tid + s]);
        __syncthreads();
    }
    mx = red[0];
    __syncthreads();

    float sum = 0.f;
    for (int i = tid; i < L; i += 256) {
        float e = __expf(smx[i] - mx);
        smx[i] = e;
        sum += e;
    }
    red[tid] = sum;
    __syncthreads();
    for (int s = 128; s > 0; s >>= 1) {
        if (tid < s) red[tid] += red[tid + s];
        __syncthreads();
    }
    const float inv = 1.f / red[0];
    __syncthreads();

    for (int i = tid; i < Lpad; i += 256)
        row[i] = __float2half_rn((i < L) ? smx[i] * inv : 0.f);
}

// ---------------------------------------------------------------------------
// Kernel 4: out = P @ V  (B side = V^T rows, seq contiguous), causal K trunc
// ---------------------------------------------------------------------------
__global__ __launch_bounds__(256, 2) void av_mma_kernel(float* __restrict__ out)
{
    const int bn = blockIdx.x, bm = blockIdx.y, b = blockIdx.z;
    const int m0 = bm << 7, n0 = bn << 7;

    float acc[4][4][4];
    ZERO_ACC(acc);
    gemm_cp(g_p + (size_t)b * S_ * S_ + (size_t)m0 * S_, S_,
            g_v + (size_t)b * D_ * S_ + (size_t)n0 * S_, S_, (bm + 1) * 4, acc);
    epilogue_f(acc, out + (size_t)b * S_ * D_ + (size_t)m0 * D_ + n0, D_);
}

// ---------------------------------------------------------------------------
extern "C" void kernel_launch(void* const* d_in, const int* in_sizes, int n_in,
                              void* d_out, int out_size)
{
    const float* query = (const float*)d_in[0];
    const float* key   = (const float*)d_in[1];
    const float* value = (const float*)d_in[2];
    // d_in[3] = causal mask (static; unused)
    const float* Wq = (const float*)d_in[4];
    const float* bq = (const float*)d_in[5];
    const float* Wk = (const float*)d_in[6];
    const float* bk = (const float*)d_in[7];
    const float* Wv = (const float*)d_in[8];
    const float* bv = (const float*)d_in[9];
    float* out = (float*)d_out;

    static int attr_done = 0;
    if (!attr_done) {
        cudaFuncSetAttribute(qkv_mma_kernel,
                             cudaFuncAttributeMaxDynamicSharedMemorySize, SM_BYTES);
        cudaFuncSetAttribute(scores_mma_kernel,
                             cudaFuncAttributeMaxDynamicSharedMemorySize, SM_BYTES);
        cudaFuncSetAttribute(av_mma_kernel,
                             cudaFuncAttributeMaxDynamicSharedMemorySize, SM_BYTES);
        attr_done = 1;
    }

    dim3 block(256);

    cvt_inputs_kernel<<<dim3(NROWS * D_ / (256 * 4), 1, 3), block>>>(query, key, value);
    wt_kernel<<<dim3(32, 32, 3), block>>>(Wq, Wk, Wv);

    qkv_mma_kernel<<<dim3(D_ / 128, NROWS / 128, 3), block, SM_BYTES>>>(bq, bk, bv);

    scores_mma_kernel<<<dim3(S_ / 128, S_ / 128, B_), block, SM_BYTES>>>();

    softmax_kernel<<<dim3(S_, B_), block>>>();

    av_mma_kernel<<<dim3(D_ / 128, S_ / 128, B_), block, SM_BYTES>>>(out);
}

// round 6
// speedup vs baseline: 6.2759x; 1.0874x over previous
#include <cuda_runtime.h>
#include <cuda_fp16.h>
#include <math.h>
#include <stdint.h>

#define B_ 8
#define S_ 2048
#define D_ 1024
#define NROWS (B_ * S_)
#define BKH 64                        // k-halves per chunk (128B per row)
#define NSTAGE 3
#define STA 72                        // halves per SMEM row (144B = 128B + 16B pad)
#define TILE_BYTES (128 * 144)        // 18432 B per operand tile
#define SM_BYTES (NSTAGE * 2 * TILE_BYTES)   // 110592 B dynamic smem

// Scratch (device globals: allowed; no runtime allocation)
__device__ __half g_xq[(size_t)NROWS * D_];   // fp16 copy of query
__device__ __half g_xk[(size_t)NROWS * D_];   // fp16 copy of key
__device__ __half g_xv[(size_t)NROWS * D_];   // fp16 copy of value
__device__ __half g_q[(size_t)NROWS * D_];    // q proj [row][d]
__device__ __half g_k[(size_t)NROWS * D_];    // k proj [row][d]
__device__ __half g_v[(size_t)NROWS * D_];    // v proj TRANSPOSED [b][d][s]
__device__ __half g_p[(size_t)B_ * S_ * S_];  // scores -> probs [b][sq][sk]
__device__ __half g_wt[3 * (size_t)D_ * D_];  // W^T fp16 [which][n][k]

// ---------------------------------------------------------------------------
// PTX helpers (base ISA: cp.async / ldmatrix / mma.sync — no tcgen05)
// ---------------------------------------------------------------------------
__device__ __forceinline__ uint32_t smem_u32(const void* p) {
    uint32_t a;
    asm("{ .reg .u64 t; cvta.to.shared.u64 t, %1; cvt.u32.u64 %0, t; }"
        : "=r"(a) : "l"(p));
    return a;
}

#define CP16(dst, src)                                                        \
    asm volatile("cp.async.cg.shared.global [%0], [%1], 16;"                  \
                 :: "r"(dst), "l"(src))
#define CP_COMMIT() asm volatile("cp.async.commit_group;" ::: "memory")
#define CP_WAIT1()  asm volatile("cp.async.wait_group 1;" ::: "memory")

#define LDMX4(r0, r1, r2, r3, addr)                                           \
    asm volatile("ldmatrix.sync.aligned.m8n8.x4.shared.b16 {%0,%1,%2,%3}, [%4];" \
                 : "=r"(r0), "=r"(r1), "=r"(r2), "=r"(r3) : "r"(addr))

#define MMA_F16(c, a, b)                                                      \
    asm volatile(                                                             \
        "mma.sync.aligned.m16n8k16.row.col.f32.f16.f16.f32 "                  \
        "{%0,%1,%2,%3}, {%4,%5,%6,%7}, {%8,%9}, {%0,%1,%2,%3};"               \
        : "+f"((c)[0]), "+f"((c)[1]), "+f"((c)[2]), "+f"((c)[3])              \
        : "r"((a)[0]), "r"((a)[1]), "r"((a)[2]), "r"((a)[3]),                 \
          "r"((b)[0]), "r"((b)[1]))

#define ZERO_ACC(acc)                                                         \
    _Pragma("unroll") for (int i = 0; i < 4; i++)                             \
    _Pragma("unroll") for (int j = 0; j < 4; j++)                             \
    _Pragma("unroll") for (int k = 0; k < 4; k++) (acc)[i][j][k] = 0.f

// ---------------------------------------------------------------------------
// cp.async one chunk: A tile 128x64h + B tile 128x64h (both [row][k] fp16).
// 8 x 16B per thread; dst rows at 144B stride (128B data + 16B pad).
// ---------------------------------------------------------------------------
__device__ __forceinline__ void issue_tile(uint32_t smA, const __half* Ag, size_t lda,
                                           uint32_t smB, const __half* Bg, size_t ldb,
                                           int j, int tid) {
#pragma unroll
    for (int w = 0; w < 4; w++) {
        const int lin = tid + (w << 8);          // 0..1023
        const int r = lin >> 3, q = lin & 7;
        CP16(smA + r * 144 + (q << 4), Ag + (size_t)r * lda + j * BKH + (q << 3));
        CP16(smB + r * 144 + (q << 4), Bg + (size_t)r * ldb + j * BKH + (q << 3));
    }
}

// ---------------------------------------------------------------------------
// Compute one K=64h chunk: 4 sub-k of 16; ldmatrix.x4 native b16 + mma k16.
// ---------------------------------------------------------------------------
__device__ __forceinline__ void compute_tile(uint32_t smA, uint32_t smB,
                                             int wm, int wn, int lane,
                                             float acc[4][4][4]) {
    const int a_row = lane & 15;
    const int a_k8  = ((lane >> 4) & 1) << 3;
    const int b_row = (lane & 7) + (((lane >> 4) & 1) << 3);
    const int b_k8  = ((lane >> 3) & 1) << 3;

#pragma unroll
    for (int k16 = 0; k16 < BKH; k16 += 16) {
        uint32_t af[4][4];
#pragma unroll
        for (int im = 0; im < 4; im++) {
            uint32_t addr = smA +
                (uint32_t)(((wm + (im << 4) + a_row) * STA + k16 + a_k8) << 1);
            LDMX4(af[im][0], af[im][1], af[im][2], af[im][3], addr);
        }
        uint32_t bf[4][2];
#pragma unroll
        for (int ip = 0; ip < 2; ip++) {
            uint32_t addr = smB +
                (uint32_t)(((wn + (ip << 4) + b_row) * STA + k16 + b_k8) << 1);
            LDMX4(bf[2 * ip][0], bf[2 * ip][1], bf[2 * ip + 1][0], bf[2 * ip + 1][1], addr);
        }
#pragma unroll
        for (int im = 0; im < 4; im++)
#pragma unroll
            for (int in = 0; in < 4; in++) MMA_F16(acc[im][in], af[im], bf[in]);
    }
}

// ---------------------------------------------------------------------------
// 3-stage cp.async pipelined mainloop, chunk K=64 halves.
// ---------------------------------------------------------------------------
__device__ __forceinline__ void gemm_cp(const __half* Ag, size_t lda,
                                        const __half* Bg, size_t ldb, int KT,
                                        float acc[4][4][4]) {
    extern __shared__ __half smh[];
    const int tid = threadIdx.x, lane = tid & 31, warp = tid >> 5;
    const int wm = (warp >> 2) << 6, wn = (warp & 3) << 5;
    const uint32_t smb = smem_u32(smh);

#pragma unroll
    for (int s = 0; s < 2; s++) {
        if (s < KT)
            issue_tile(smb + s * 2 * TILE_BYTES, Ag, lda,
                       smb + s * 2 * TILE_BYTES + TILE_BYTES, Bg, ldb, s, tid);
        CP_COMMIT();
    }
    for (int j = 0; j < KT; ++j) {
        CP_WAIT1();
        __syncthreads();
        const int jn = j + 2;
        if (jn < KT) {
            const int bs = jn % NSTAGE;
            issue_tile(smb + bs * 2 * TILE_BYTES, Ag, lda,
                       smb + bs * 2 * TILE_BYTES + TILE_BYTES, Bg, ldb, jn, tid);
        }
        CP_COMMIT();
        const int cs = j % NSTAGE;
        compute_tile(smb + cs * 2 * TILE_BYTES,
                     smb + cs * 2 * TILE_BYTES + TILE_BYTES, wm, wn, lane, acc);
    }
}

// ---------------------------------------------------------------------------
// Epilogues (acc frag: c0,c1 @ row g cols 2t,2t+1; c2,c3 @ row g+8)
// ---------------------------------------------------------------------------
__device__ __forceinline__ void epilogue_h(float acc[4][4][4], __half* out, size_t ld,
                                           const float* bias, float scale) {
    const int lane = threadIdx.x & 31, warp = threadIdx.x >> 5;
    const int g = lane >> 2, t = lane & 3;
    const int wm = (warp >> 2) << 6, wn = (warp & 3) << 5;
#pragma unroll
    for (int im = 0; im < 4; im++) {
#pragma unroll
        for (int in = 0; in < 4; in++) {
            const int r0 = wm + (im << 4) + g;
            const int c = wn + (in << 3) + (t << 1);
            const float b0 = bias ? bias[c] : 0.f;
            const float b1 = bias ? bias[c + 1] : 0.f;
            *(__half2*)(out + (size_t)r0 * ld + c) =
                __floats2half2_rn(acc[im][in][0] * scale + b0,
                                  acc[im][in][1] * scale + b1);
            *(__half2*)(out + (size_t)(r0 + 8) * ld + c) =
                __floats2half2_rn(acc[im][in][2] * scale + b0,
                                  acc[im][in][3] * scale + b1);
        }
    }
}

__device__ __forceinline__ void epilogue_f(float acc[4][4][4], float* out, size_t ld) {
    const int lane = threadIdx.x & 31, warp = threadIdx.x >> 5;
    const int g = lane >> 2, t = lane & 3;
    const int wm = (warp >> 2) << 6, wn = (warp & 3) << 5;
#pragma unroll
    for (int im = 0; im < 4; im++) {
#pragma unroll
        for (int in = 0; in < 4; in++) {
            const int r0 = wm + (im << 4) + g;
            const int c = wn + (in << 3) + (t << 1);
            *(float2*)(out + (size_t)r0 * ld + c) =
                make_float2(acc[im][in][0], acc[im][in][1]);
            *(float2*)(out + (size_t)(r0 + 8) * ld + c) =
                make_float2(acc[im][in][2], acc[im][in][3]);
        }
    }
}

// Transposed store for V: vt is [D][S] for this batch (fp16).
__device__ __forceinline__ void epilogue_vt(float acc[4][4][4], __half* vt,
                                            int mloc, int n0, const float* bias) {
    const int lane = threadIdx.x & 31, warp = threadIdx.x >> 5;
    const int g = lane >> 2, t = lane & 3;
    const int wm = (warp >> 2) << 6, wn = (warp & 3) << 5;
#pragma unroll
    for (int im = 0; im < 4; im++) {
#pragma unroll
        for (int in = 0; in < 4; in++) {
            const int r = mloc + wm + (im << 4) + g;
            const int c = n0 + wn + (in << 3) + (t << 1);
            const float b0 = bias[c], b1 = bias[c + 1];
            vt[(size_t)c * S_ + r]           = __float2half_rn(acc[im][in][0] + b0);
            vt[(size_t)(c + 1) * S_ + r]     = __float2half_rn(acc[im][in][1] + b1);
            vt[(size_t)c * S_ + r + 8]       = __float2half_rn(acc[im][in][2] + b0);
            vt[(size_t)(c + 1) * S_ + r + 8] = __float2half_rn(acc[im][in][3] + b1);
        }
    }
}

// ---------------------------------------------------------------------------
// Kernel 0a: fp32 -> fp16 convert of raw query/key/value
// ---------------------------------------------------------------------------
__global__ __launch_bounds__(256) void cvt_inputs_kernel(
    const float* __restrict__ q, const float* __restrict__ k,
    const float* __restrict__ v) {
    const int z = blockIdx.z;
    const float* src = (z == 0) ? q : (z == 1) ? k : v;
    __half* dst = (z == 0) ? g_xq : (z == 1) ? g_xk : g_xv;
    const size_t i = ((size_t)blockIdx.x * 256 + threadIdx.x) * 4;
    float4 f = *(const float4*)(src + i);
    __half2* d2 = (__half2*)(dst + i);
    d2[0] = __floats2half2_rn(f.x, f.y);
    d2[1] = __floats2half2_rn(f.z, f.w);
}

// ---------------------------------------------------------------------------
// Kernel 0b: W ([k][n] fp32) -> g_wt ([n][k] fp16)
// ---------------------------------------------------------------------------
__global__ __launch_bounds__(256) void wt_kernel(const float* __restrict__ Wq,
                                                 const float* __restrict__ Wk,
                                                 const float* __restrict__ Wv) {
    const int z = blockIdx.z;
    const float* W = (z == 0) ? Wq : (z == 1) ? Wk : Wv;
    __half* WT = g_wt + (size_t)z * D_ * D_;
    __shared__ float t[32][33];
    const int tx = threadIdx.x & 31, ty = threadIdx.x >> 5;
    const int x0 = blockIdx.x << 5, y0 = blockIdx.y << 5;
#pragma unroll
    for (int i = 0; i < 4; i++)
        t[ty + i * 8][tx] = W[(size_t)(y0 + ty + i * 8) * D_ + x0 + tx];
    __syncthreads();
#pragma unroll
    for (int i = 0; i < 4; i++)
        WT[(size_t)(x0 + ty + i * 8) * D_ + y0 + tx] = __float2half_rn(t[tx][ty + i * 8]);
}

// ---------------------------------------------------------------------------
// Kernel 1: QKV projection  C = X @ W + b
// ---------------------------------------------------------------------------
__global__ __launch_bounds__(256, 2) void qkv_mma_kernel(
    const float* __restrict__ bq, const float* __restrict__ bk,
    const float* __restrict__ bv)
{
    const int which = blockIdx.z;
    const __half* A   = (which == 0) ? g_xq : (which == 1) ? g_xk : g_xv;
    const float* bias = (which == 0) ? bq   : (which == 1) ? bk   : bv;

    const int m0 = blockIdx.y << 7, n0 = blockIdx.x << 7;
    float acc[4][4][4];
    ZERO_ACC(acc);
    gemm_cp(A + (size_t)m0 * D_, D_,
            g_wt + (size_t)which * D_ * D_ + (size_t)n0 * D_, D_, D_ / BKH, acc);

    if (which == 2) {
        const int b = m0 >> 11;
        epilogue_vt(acc, g_v + (size_t)b * D_ * S_, m0 & (S_ - 1), n0, bias);
    } else {
        __half* C = (which == 0) ? g_q : g_k;
        epilogue_h(acc, C + (size_t)m0 * D_ + n0, D_, bias + n0, 1.0f);
    }
}

// ---------------------------------------------------------------------------
// Kernel 2: scores = (Q @ K^T)/32, lower-triangular blocks only
// ---------------------------------------------------------------------------
__global__ __launch_bounds__(256, 2) void scores_mma_kernel()
{
    const int bn = blockIdx.x, bm = blockIdx.y, b = blockIdx.z;
    if (bn > bm) return;
    const int m0 = bm << 7, n0 = bn << 7;

    float acc[4][4][4];
    ZERO_ACC(acc);
    gemm_cp(g_q + (size_t)b * S_ * D_ + (size_t)m0 * D_, D_,
            g_k + (size_t)b * S_ * D_ + (size_t)n0 * D_, D_, D_ / BKH, acc);
    epilogue_h(acc, g_p + (size_t)b * S_ * S_ + (size_t)m0 * S_ + n0, S_,
               nullptr, 0.03125f);
}

// ---------------------------------------------------------------------------
// Kernel 3: causal row softmax on fp16 P; zero-pads [L, Lpad)
// ---------------------------------------------------------------------------
__global__ __launch_bounds__(256) void softmax_kernel()
{
    const int m = blockIdx.x;
    const int b = blockIdx.y;
    __half* row = g_p + ((size_t)b * S_ + m) * S_;
    const int L = m + 1;
    const int Lpad = ((m >> 7) + 1) << 7;

    __shared__ float smx[S_];
    __shared__ float red[256];
    const int tid = threadIdx.x;

    float mx = -INFINITY;
    for (int i = tid; i < L; i += 256) {
        float v = __half2float(row[i]);
        smx[i] = v;
        mx = fmaxf(mx, v);
    }
    red[tid] = mx;
    __syncthreads();
    for (int s = 128; s > 0; s >>= 1) {
        if (tid < s) red[tid] = fmaxf(red[tid], red[tid + s]);
        __syncthreads();
    }
    mx = red[0];
    __syncthreads();

    float sum = 0.f;
    for (int i = tid; i < L; i += 256) {
        float e = __expf(smx[i] - mx);
        smx[i] = e;
        sum += e;
    }
    red[tid] = sum;
    __syncthreads();
    for (int s = 128; s > 0; s >>= 1) {
        if (tid < s) red[tid] += red[tid + s];
        __syncthreads();
    }
    const float inv = 1.f / red[0];
    __syncthreads();

    for (int i = tid; i < Lpad; i += 256)
        row[i] = __float2half_rn((i < L) ? smx[i] * inv : 0.f);
}

// ---------------------------------------------------------------------------
// Kernel 4: out = P @ V  (B side = V^T rows, seq contiguous), causal K trunc
// ---------------------------------------------------------------------------
__global__ __launch_bounds__(256, 2) void av_mma_kernel(float* __restrict__ out)
{
    const int bn = blockIdx.x, bm = blockIdx.y, b = blockIdx.z;
    const int m0 = bm << 7, n0 = bn << 7;

    float acc[4][4][4];
    ZERO_ACC(acc);
    gemm_cp(g_p + (size_t)b * S_ * S_ + (size_t)m0 * S_, S_,
            g_v + (size_t)b * D_ * S_ + (size_t)n0 * S_, S_, (bm + 1) * 2, acc);
    epilogue_f(acc, out + (size_t)b * S_ * D_ + (size_t)m0 * D_ + n0, D_);
}

// ---------------------------------------------------------------------------
extern "C" void kernel_launch(void* const* d_in, const int* in_sizes, int n_in,
                              void* d_out, int out_size)
{
    const float* query = (const float*)d_in[0];
    const float* key   = (const float*)d_in[1];
    const float* value = (const float*)d_in[2];
    // d_in[3] = causal mask (static; unused)
    const float* Wq = (const float*)d_in[4];
    const float* bq = (const float*)d_in[5];
    const float* Wk = (const float*)d_in[6];
    const float* bk = (const float*)d_in[7];
    const float* Wv = (const float*)d_in[8];
    const float* bv = (const float*)d_in[9];
    float* out = (float*)d_out;

    static int attr_done = 0;
    if (!attr_done) {
        cudaFuncSetAttribute(qkv_mma_kernel,
                             cudaFuncAttributeMaxDynamicSharedMemorySize, SM_BYTES);
        cudaFuncSetAttribute(scores_mma_kernel,
                             cudaFuncAttributeMaxDynamicSharedMemorySize, SM_BYTES);
        cudaFuncSetAttribute(av_mma_kernel,
                             cudaFuncAttributeMaxDynamicSharedMemorySize, SM_BYTES);
        attr_done = 1;
    }

    dim3 block(256);

    cvt_inputs_kernel<<<dim3(NROWS * D_ / (256 * 4), 1, 3), block>>>(query, key, value);
    wt_kernel<<<dim3(32, 32, 3), block>>>(Wq, Wk, Wv);

    qkv_mma_kernel<<<dim3(D_ / 128, NROWS / 128, 3), block, SM_BYTES>>>(bq, bk, bv);

    scores_mma_kernel<<<dim3(S_ / 128, S_ / 128, B_), block, SM_BYTES>>>();

    softmax_kernel<<<dim3(S_, B_), block>>>();

    av_mma_kernel<<<dim3(D_ / 128, S_ / 128, B_), block, SM_BYTES>>>(out);
}